// round 6
// baseline (speedup 1.0000x reference)
#include <cuda_runtime.h>
#include <cuda_bf16.h>
#include <math.h>
#include <stdint.h>

#define VOCAB 100000
#define EMB   300
#define HID   256
#define BATCH 64
#define SEQ   512
#define NROWS (SEQ*BATCH)   /* 32768 */
#define GCOLS 2048          /* 2 dirs * 4 gates * 256 */

// ---------------- static scratch (no allocations allowed) -------------------
__device__ float d_G [(size_t)NROWS * GCOLS];   // 256 MB gate preactivations
__device__ float d_Y0[(size_t)NROWS * 512];     // layer-0 output (t,b,2H)
__device__ float d_Y1[(size_t)NROWS * 512];     // layer-1 output (t,b,2H)

// ============================================================================
// GEMM: d_G[r][c] = sum_k A[r][k]*W[c][k] + bias1[c] + bias2[c]
//   mode 0: A row r = emb[contexts[b][t]], r = t*64+b, K=300
//   mode 1: A row r = d_Y0[r][:], K=512
// 128x128 tile, BK=8, 8x8 microtile, 256 threads.
// ============================================================================
__global__ void __launch_bounds__(256)
gemm_inp(const float* __restrict__ emb, const int* __restrict__ tokens,
         const float* __restrict__ W,
         const float* __restrict__ bias1, const float* __restrict__ bias2,
         int K, int mode)
{
    __shared__ float As[8][128];
    __shared__ float Bs[8][128];
    __shared__ int   toks[128];

    const int bm = blockIdx.y;   // 0..255
    const int bn = blockIdx.x;   // 0..15
    const int tid = threadIdx.x;

    if (mode == 0 && tid < 128) {
        int r = bm * 128 + tid;            // r = t*64+b
        int b = r & 63, t = r >> 6;
        toks[tid] = tokens[b * SEQ + t];
    }
    __syncthreads();

    float acc[8][8];
#pragma unroll
    for (int i = 0; i < 8; i++)
#pragma unroll
        for (int jj = 0; jj < 8; jj++) acc[i][jj] = 0.0f;

    const int arow = tid >> 1, ak4 = tid & 1;
    const int tx = tid & 15, ty = tid >> 4;

    for (int k0 = 0; k0 < K; k0 += 8) {
        // A tile (transposed into smem)
        {
            const float* ap;
            if (mode == 0) ap = emb + (size_t)toks[arow] * EMB;
            else           ap = d_Y0 + (size_t)(bm * 128 + arow) * 512;
            int k = k0 + ak4 * 4;
            float4 v = make_float4(0.f, 0.f, 0.f, 0.f);
            if (k + 3 < K) v = *(const float4*)(ap + k);
            else {
                if (k + 0 < K) v.x = ap[k + 0];
                if (k + 1 < K) v.y = ap[k + 1];
                if (k + 2 < K) v.z = ap[k + 2];
            }
            As[ak4*4+0][arow] = v.x; As[ak4*4+1][arow] = v.y;
            As[ak4*4+2][arow] = v.z; As[ak4*4+3][arow] = v.w;
        }
        // B tile: W rows (transposed)
        {
            const float* wp = W + (size_t)(bn * 128 + arow) * K;
            int k = k0 + ak4 * 4;
            float4 v = make_float4(0.f, 0.f, 0.f, 0.f);
            if (k + 3 < K) v = *(const float4*)(wp + k);
            else {
                if (k + 0 < K) v.x = wp[k + 0];
                if (k + 1 < K) v.y = wp[k + 1];
                if (k + 2 < K) v.z = wp[k + 2];
            }
            Bs[ak4*4+0][arow] = v.x; Bs[ak4*4+1][arow] = v.y;
            Bs[ak4*4+2][arow] = v.z; Bs[ak4*4+3][arow] = v.w;
        }
        __syncthreads();

#pragma unroll
        for (int kk = 0; kk < 8; kk++) {
            float a[8], bb[8];
            *(float4*)&a[0]  = *(const float4*)&As[kk][ty*8];
            *(float4*)&a[4]  = *(const float4*)&As[kk][ty*8+4];
            *(float4*)&bb[0] = *(const float4*)&Bs[kk][tx*8];
            *(float4*)&bb[4] = *(const float4*)&Bs[kk][tx*8+4];
#pragma unroll
            for (int i = 0; i < 8; i++)
#pragma unroll
                for (int jj = 0; jj < 8; jj++)
                    acc[i][jj] = fmaf(a[i], bb[jj], acc[i][jj]);
        }
        __syncthreads();
    }

#pragma unroll
    for (int i = 0; i < 8; i++) {
        size_t r = (size_t)(bm * 128 + ty * 8 + i);
#pragma unroll
        for (int j4 = 0; j4 < 2; j4++) {
            int c0 = bn * 128 + tx * 8 + j4 * 4;
            float4 o;
            o.x = acc[i][j4*4+0] + bias1[c0+0] + bias2[c0+0];
            o.y = acc[i][j4*4+1] + bias1[c0+1] + bias2[c0+1];
            o.z = acc[i][j4*4+2] + bias1[c0+2] + bias2[c0+2];
            o.w = acc[i][j4*4+3] + bias1[c0+3] + bias2[c0+3];
            *(float4*)&d_G[r * GCOLS + c0] = o;
        }
    }
}

// ============================================================================
// Persistent LSTM recurrence. 128 CTAs = 16 clusters of 8.
//  cluster rank hc -> h columns [hc*32, hc*32+32); cluster id -> (dir, 8-batch chunk)
//  Thread (j=tid&31, g=(tid>>5)&3, kh=tid>>7) holds W_hh[d][g*256+hc*32+j][kh*128..+128)
//  in 32 float4 registers. c in a register. h exchanged via DSMEM push +
//  one cluster barrier per step (release/acquire orders the remote stores).
// ============================================================================
__global__ void __cluster_dims__(8,1,1) __launch_bounds__(256,1)
lstm_rec(const float* __restrict__ whh, int layer)
{
    __shared__ float h_sm[2][8][256];      // double-buffered h (8 batch x 256)
    __shared__ float ps[2][4][8][32];      // k-half partial gates

    float* Y = layer ? d_Y1 : d_Y0;
    const int tid = threadIdx.x;
    const int j  = tid & 31;
    const int g  = (tid >> 5) & 3;
    const int kh = tid >> 7;
    const int hc = blockIdx.x & 7;
    const int cid = blockIdx.x >> 3;
    const int d  = cid & 1;
    const int B0 = (cid >> 1) * 8;

    // cache W_hh slice in registers (once)
    float4 w[32];
    {
        const float4* wp = (const float4*)
            (whh + ((size_t)d*1024 + g*256 + hc*32 + j) * 256 + kh*128);
#pragma unroll
        for (int kk = 0; kk < 32; kk++) w[kk] = wp[kk];
    }
    // zero both h buffers
    {
        float* hz = &h_sm[0][0][0];
        for (int i = tid; i < 2*8*256; i += 256) hz[i] = 0.f;
    }
    const int ub = tid >> 5, uj = tid & 31;
    float creg = 0.f;
    __syncthreads();
    asm volatile("barrier.cluster.arrive.aligned;" ::: "memory");
    asm volatile("barrier.cluster.wait.aligned;"   ::: "memory");

    uint32_t base_l0 = (uint32_t)__cvta_generic_to_shared(&h_sm[0][ub][hc*32+uj]);
    uint32_t base_l1 = (uint32_t)__cvta_generic_to_shared(&h_sm[1][ub][hc*32+uj]);
    const int kq0 = kh * 32;

    for (int t = 0; t < SEQ; t++) {
        const int p = t & 1;
        // prefetch gate preactivations for the update phase
        size_t gb = ((size_t)t*64 + B0 + ub) * GCOLS + (size_t)d*1024 + hc*32 + uj;
        float gp0 = d_G[gb];
        float gp1 = d_G[gb + 256];
        float gp2 = d_G[gb + 512];
        float gp3 = d_G[gb + 768];

        // h @ W_hh^T partials: weights in regs, h broadcast from smem
        const float4* hb = (const float4*)&h_sm[p][0][0];
        float acc[8];
#pragma unroll
        for (int b = 0; b < 8; b++) acc[b] = 0.f;
#pragma unroll
        for (int kk = 0; kk < 32; kk++) {
            float4 wv = w[kk];
#pragma unroll
            for (int b = 0; b < 8; b++) {
                float4 hv = hb[b*64 + kq0 + kk];
                acc[b] = fmaf(wv.x, hv.x, acc[b]);
                acc[b] = fmaf(wv.y, hv.y, acc[b]);
                acc[b] = fmaf(wv.z, hv.z, acc[b]);
                acc[b] = fmaf(wv.w, hv.w, acc[b]);
            }
        }
#pragma unroll
        for (int b = 0; b < 8; b++) ps[kh][g][b][j] = acc[b];
        __syncthreads();

        // elementwise cell update: thread owns (batch B0+ub, h-col hc*32+uj)
        float si = ps[0][0][ub][uj] + ps[1][0][ub][uj] + gp0;
        float sf = ps[0][1][ub][uj] + ps[1][1][ub][uj] + gp1;
        float sg = ps[0][2][ub][uj] + ps[1][2][ub][uj] + gp2;
        float so = ps[0][3][ub][uj] + ps[1][3][ub][uj] + gp3;
        float iv = 1.f / (1.f + expf(-si));
        float fv = 1.f / (1.f + expf(-sf));
        float ov = 1.f / (1.f + expf(-so));
        creg = fv * creg + iv * tanhf(sg);
        float hnew = ov * tanhf(creg);

        Y[((size_t)t*64 + B0 + ub) * 512 + (size_t)d*256 + hc*32 + uj] = hnew;

        // push hnew into next-parity buffer of ALL cluster CTAs (incl. self)
        uint32_t la = p ? base_l0 : base_l1;
#pragma unroll
        for (unsigned r = 0; r < 8; r++) {
            uint32_t ra;
            asm volatile("mapa.shared::cluster.u32 %0, %1, %2;"
                         : "=r"(ra) : "r"(la), "r"(r));
            asm volatile("st.shared::cluster.f32 [%0], %1;"
                         :: "r"(ra), "f"(hnew) : "memory");
        }
        asm volatile("barrier.cluster.arrive.aligned;" ::: "memory");
        asm volatile("barrier.cluster.wait.aligned;"   ::: "memory");
    }
}

// ============================================================================
// Epilogue: gather at positions, classifier, sigmoid.
// out layout: logits(64x2) | probs(64x2) | target(64x512)
// ============================================================================
__global__ void __launch_bounds__(512)
epilogue(const int* __restrict__ pos, const float* __restrict__ wcls,
         const float* __restrict__ bcls, float* __restrict__ out)
{
    __shared__ float s0[512], s1[512];
    int b = blockIdx.x, i = threadIdx.x;
    int t = pos[b];
    float y = d_Y1[((size_t)t*64 + b) * 512 + i];
    out[256 + b*512 + i] = y;
    s0[i] = y * wcls[i];
    s1[i] = y * wcls[512 + i];
    __syncthreads();
    for (int st = 256; st > 0; st >>= 1) {
        if (i < st) { s0[i] += s0[i+st]; s1[i] += s1[i+st]; }
        __syncthreads();
    }
    if (i == 0) {
        float l0 = s0[0] + bcls[0], l1 = s1[0] + bcls[1];
        out[b*2+0] = l0;            out[b*2+1] = l1;
        out[128 + b*2+0] = 1.f/(1.f+expf(-l0));
        out[128 + b*2+1] = 1.f/(1.f+expf(-l1));
    }
}

// ============================================================================
extern "C" void kernel_launch(void* const* d_in, const int* in_sizes, int n_in,
                              void* d_out, int out_size)
{
    const float *emb=0,*wih0=0,*whh0=0,*bih0=0,*bhh0=0;
    const float *wih1=0,*whh1=0,*bih1=0,*bhh1=0,*wcls=0,*bcls=0;
    const int *ctx=0,*pos=0;
    int nwhh = 0, nb = 0;
    for (int i = 0; i < n_in; i++) {
        int s = in_sizes[i]; const void* p = d_in[i];
        switch (s) {
            case 30000000: emb  = (const float*)p; break;
            case 614400:   wih0 = (const float*)p; break;
            case 1048576:  wih1 = (const float*)p; break;
            case 524288:   if (nwhh++ == 0) whh0 = (const float*)p;
                           else             whh1 = (const float*)p; break;
            case 2048:     if (nb == 0) bih0 = (const float*)p;
                           else if (nb == 1) bhh0 = (const float*)p;
                           else if (nb == 2) bih1 = (const float*)p;
                           else              bhh1 = (const float*)p;
                           nb++; break;
            case 1024:     wcls = (const float*)p; break;
            case 2:        bcls = (const float*)p; break;
            case 32768:    ctx  = (const int*)p; break;
            case 64:       pos  = (const int*)p; break;
            default: break;
        }
    }

    dim3 ggrid(16, 256);
    // Layer 0: input projections + recurrence
    gemm_inp<<<ggrid, 256>>>(emb, ctx, wih0, bih0, bhh0, EMB, 0);
    lstm_rec<<<128, 256>>>(whh0, 0);
    // Layer 1
    gemm_inp<<<ggrid, 256>>>(emb, ctx, wih1, bih1, bhh1, 512, 1);
    lstm_rec<<<128, 256>>>(whh1, 1);
    // Classifier
    epilogue<<<64, 512>>>(pos, wcls, bcls, (float*)d_out);
}

// round 7
// speedup vs baseline: 1.0427x; 1.0427x over previous
#include <cuda_runtime.h>
#include <cuda_bf16.h>
#include <math.h>
#include <stdint.h>

#define VOCAB 100000
#define EMB   300
#define HID   256
#define BATCH 64
#define SEQ   512
#define NROWS (SEQ*BATCH)   /* 32768 */
#define GCOLS 2048          /* 2 dirs * 4 gates * 256 */

// ---------------- static scratch (no allocations allowed) -------------------
__device__ float d_G [(size_t)NROWS * GCOLS];   // gate preactivations
__device__ float d_Y0[(size_t)NROWS * 512];     // layer-0 output (t,b,2H)
__device__ float d_Y1[(size_t)NROWS * 512];     // layer-1 output (t,b,2H)

// ---------------- packed fp32x2 helpers (B300 dual-fp32 path) ---------------
__device__ __forceinline__ void fma2(unsigned long long& acc,
                                     unsigned long long a, unsigned long long b) {
    asm("fma.rn.f32x2 %0, %1, %2, %0;" : "+l"(acc) : "l"(a), "l"(b));
}
__device__ __forceinline__ unsigned long long dup2(float x) {
    unsigned long long r; unsigned u = __float_as_uint(x);
    asm("mov.b64 %0, {%1, %1};" : "=l"(r) : "r"(u));
    return r;
}
__device__ __forceinline__ float2 unpk(unsigned long long v) {
    float2 f;
    asm("mov.b64 {%0, %1}, %2;" : "=f"(f.x), "=f"(f.y) : "l"(v));
    return f;
}

// ============================================================================
// GEMM: d_G[r][c] = sum_k A[r][k]*W[c][k] + bias1[c] + bias2[c]
//   mode 0: A row r = emb[contexts[b][t]], r = t*64+b, K=300
//   mode 1: A row r = d_Y0[r][:], K=512
// 128x128 tile, BK=8, 8x8 microtile via f32x2 (pairs along M), 256 threads,
// double-buffered smem.
// ============================================================================
__global__ void __launch_bounds__(256)
gemm_inp(const float* __restrict__ emb, const int* __restrict__ tokens,
         const float* __restrict__ W,
         const float* __restrict__ bias1, const float* __restrict__ bias2,
         int K, int mode)
{
    __shared__ __align__(16) float As[2][8][128];
    __shared__ __align__(16) float Bs[2][8][128];
    __shared__ int toks[128];

    const int bm = blockIdx.y;   // 0..255
    const int bn = blockIdx.x;   // 0..15
    const int tid = threadIdx.x;

    if (mode == 0 && tid < 128) {
        int r = bm * 128 + tid;            // r = t*64+b
        int b = r & 63, t = r >> 6;
        toks[tid] = tokens[b * SEQ + t];
    }
    __syncthreads();

    // accumulators: acc2[i2][j] = rows (ty*8+2*i2, +1) x col (tx*8+j), k-paired by M
    unsigned long long acc2[4][8];
#pragma unroll
    for (int i = 0; i < 4; i++)
#pragma unroll
        for (int j = 0; j < 8; j++) acc2[i][j] = 0ull;

    const int arow = tid >> 1, ak4 = tid & 1;
    const int tx = tid & 15, ty = tid >> 4;

    const float* arp;
    if (mode == 0) arp = emb + (size_t)toks[arow] * EMB;
    else           arp = d_Y0 + (size_t)(bm * 128 + arow) * 512;
    const float* brp = W + (size_t)(bn * 128 + arow) * K;

    const int nIter = (K + 7) / 8;

    // ---- prologue: load tile 0 ----
    float4 va, vb;
    {
        int k = 0 + ak4 * 4;
        va = make_float4(0.f,0.f,0.f,0.f); vb = va;
        if (k + 3 < K) { va = *(const float4*)(arp + k); vb = *(const float4*)(brp + k); }
        else {
            if (k+0 < K) { va.x = arp[k+0]; vb.x = brp[k+0]; }
            if (k+1 < K) { va.y = arp[k+1]; vb.y = brp[k+1]; }
            if (k+2 < K) { va.z = arp[k+2]; vb.z = brp[k+2]; }
        }
        As[0][ak4*4+0][arow]=va.x; As[0][ak4*4+1][arow]=va.y;
        As[0][ak4*4+2][arow]=va.z; As[0][ak4*4+3][arow]=va.w;
        Bs[0][ak4*4+0][arow]=vb.x; Bs[0][ak4*4+1][arow]=vb.y;
        Bs[0][ak4*4+2][arow]=vb.z; Bs[0][ak4*4+3][arow]=vb.w;
    }
    __syncthreads();

    for (int it = 0; it < nIter; it++) {
        const int p = it & 1;
        const bool more = (it + 1 < nIter);
        if (more) {
            int k = (it + 1) * 8 + ak4 * 4;
            va = make_float4(0.f,0.f,0.f,0.f); vb = va;
            if (k + 3 < K) { va = *(const float4*)(arp + k); vb = *(const float4*)(brp + k); }
            else {
                if (k+0 < K) { va.x = arp[k+0]; vb.x = brp[k+0]; }
                if (k+1 < K) { va.y = arp[k+1]; vb.y = brp[k+1]; }
                if (k+2 < K) { va.z = arp[k+2]; vb.z = brp[k+2]; }
            }
        }

#pragma unroll
        for (int kk = 0; kk < 8; kk++) {
            const ulonglong2* ap = (const ulonglong2*)&As[p][kk][ty*8];
            ulonglong2 a01 = ap[0];
            ulonglong2 a23 = ap[1];
            float bf[8];
            *(float4*)&bf[0] = *(const float4*)&Bs[p][kk][tx*8];
            *(float4*)&bf[4] = *(const float4*)&Bs[p][kk][tx*8+4];
#pragma unroll
            for (int j = 0; j < 8; j++) {
                unsigned long long bd = dup2(bf[j]);
                fma2(acc2[0][j], a01.x, bd);
                fma2(acc2[1][j], a01.y, bd);
                fma2(acc2[2][j], a23.x, bd);
                fma2(acc2[3][j], a23.y, bd);
            }
        }

        if (more) {
            const int q = p ^ 1;
            As[q][ak4*4+0][arow]=va.x; As[q][ak4*4+1][arow]=va.y;
            As[q][ak4*4+2][arow]=va.z; As[q][ak4*4+3][arow]=va.w;
            Bs[q][ak4*4+0][arow]=vb.x; Bs[q][ak4*4+1][arow]=vb.y;
            Bs[q][ak4*4+2][arow]=vb.z; Bs[q][ak4*4+3][arow]=vb.w;
        }
        __syncthreads();
    }

    // ---- epilogue: unpack, add biases, store ----
#pragma unroll
    for (int i2 = 0; i2 < 4; i2++) {
        float lo[8], hi[8];
#pragma unroll
        for (int j = 0; j < 8; j++) {
            float2 u = unpk(acc2[i2][j]);
            lo[j] = u.x; hi[j] = u.y;
        }
#pragma unroll
        for (int half = 0; half < 2; half++) {
            const float* f = half ? hi : lo;
            size_t r = (size_t)(bm * 128 + ty * 8 + i2 * 2 + half);
#pragma unroll
            for (int j4 = 0; j4 < 2; j4++) {
                int c0 = bn * 128 + tx * 8 + j4 * 4;
                float4 o;
                o.x = f[j4*4+0] + bias1[c0+0] + bias2[c0+0];
                o.y = f[j4*4+1] + bias1[c0+1] + bias2[c0+1];
                o.z = f[j4*4+2] + bias1[c0+2] + bias2[c0+2];
                o.w = f[j4*4+3] + bias1[c0+3] + bias2[c0+3];
                *(float4*)&d_G[r * GCOLS + c0] = o;
            }
        }
    }
}

// ============================================================================
// Persistent LSTM recurrence. 128 CTAs = 16 clusters of 8.
//  cluster rank hc -> h columns [hc*32, hc*32+32); cluster id -> (dir, 8-batch chunk)
//  Thread (j=tid&31, g=(tid>>5)&3, kh=tid>>7) holds its 128-float W_hh slice in
//  32 ulonglong2 registers; the h@W_hh partial is computed with fma.rn.f32x2
//  (accumulator = two k-partials, reduced at the end). h exchanged via DSMEM
//  push + one cluster barrier per step.
// ============================================================================
__global__ void __cluster_dims__(8,1,1) __launch_bounds__(256,1)
lstm_rec(const float* __restrict__ whh, int layer)
{
    __shared__ __align__(16) float h_sm[2][8][256]; // double-buffered h
    __shared__ float ps[2][4][8][32];               // k-half partial gates

    float* Y = layer ? d_Y1 : d_Y0;
    const int tid = threadIdx.x;
    const int j  = tid & 31;
    const int g  = (tid >> 5) & 3;
    const int kh = tid >> 7;
    const int hc = blockIdx.x & 7;
    const int cid = blockIdx.x >> 3;
    const int d  = cid & 1;
    const int B0 = (cid >> 1) * 8;

    // cache W_hh slice in registers (once), as packed f32x2 pairs
    ulonglong2 w2[32];
    {
        const ulonglong2* wp = (const ulonglong2*)
            (whh + ((size_t)d*1024 + g*256 + hc*32 + j) * 256 + kh*128);
#pragma unroll
        for (int kk = 0; kk < 32; kk++) w2[kk] = wp[kk];
    }
    // zero both h buffers
    {
        float* hz = &h_sm[0][0][0];
        for (int i = tid; i < 2*8*256; i += 256) hz[i] = 0.f;
    }
    const int ub = tid >> 5, uj = tid & 31;
    float creg = 0.f;
    __syncthreads();
    asm volatile("barrier.cluster.arrive.aligned;" ::: "memory");
    asm volatile("barrier.cluster.wait.aligned;"   ::: "memory");

    uint32_t base_l0 = (uint32_t)__cvta_generic_to_shared(&h_sm[0][ub][hc*32+uj]);
    uint32_t base_l1 = (uint32_t)__cvta_generic_to_shared(&h_sm[1][ub][hc*32+uj]);
    const int kq0 = kh * 32;

    for (int t = 0; t < SEQ; t++) {
        const int p = t & 1;
        // prefetch gate preactivations for the update phase (hidden by FMA phase)
        size_t gb = ((size_t)t*64 + B0 + ub) * GCOLS + (size_t)d*1024 + hc*32 + uj;
        float gp0 = d_G[gb];
        float gp1 = d_G[gb + 256];
        float gp2 = d_G[gb + 512];
        float gp3 = d_G[gb + 768];

        // h @ W_hh^T partials via packed f32x2 (weights in regs, h from smem)
        const ulonglong2* hb = (const ulonglong2*)&h_sm[p][0][0];
        unsigned long long acc2[8];
#pragma unroll
        for (int b = 0; b < 8; b++) acc2[b] = 0ull;
#pragma unroll
        for (int kk = 0; kk < 32; kk++) {
            ulonglong2 wv = w2[kk];
#pragma unroll
            for (int b = 0; b < 8; b++) {
                ulonglong2 hv = hb[b*64 + kq0 + kk];
                fma2(acc2[b], wv.x, hv.x);
                fma2(acc2[b], wv.y, hv.y);
            }
        }
#pragma unroll
        for (int b = 0; b < 8; b++) {
            float2 u = unpk(acc2[b]);
            ps[kh][g][b][j] = u.x + u.y;
        }
        __syncthreads();

        // elementwise cell update: thread owns (batch B0+ub, h-col hc*32+uj)
        float si = ps[0][0][ub][uj] + ps[1][0][ub][uj] + gp0;
        float sf = ps[0][1][ub][uj] + ps[1][1][ub][uj] + gp1;
        float sg = ps[0][2][ub][uj] + ps[1][2][ub][uj] + gp2;
        float so = ps[0][3][ub][uj] + ps[1][3][ub][uj] + gp3;
        float iv = 1.f / (1.f + expf(-si));
        float fv = 1.f / (1.f + expf(-sf));
        float ov = 1.f / (1.f + expf(-so));
        creg = fv * creg + iv * tanhf(sg);
        float hnew = ov * tanhf(creg);

        Y[((size_t)t*64 + B0 + ub) * 512 + (size_t)d*256 + hc*32 + uj] = hnew;

        // push hnew into next-parity buffer of ALL cluster CTAs (incl. self)
        uint32_t la = p ? base_l0 : base_l1;
#pragma unroll
        for (unsigned r = 0; r < 8; r++) {
            uint32_t ra;
            asm volatile("mapa.shared::cluster.u32 %0, %1, %2;"
                         : "=r"(ra) : "r"(la), "r"(r));
            asm volatile("st.shared::cluster.f32 [%0], %1;"
                         :: "r"(ra), "f"(hnew) : "memory");
        }
        asm volatile("barrier.cluster.arrive.aligned;" ::: "memory");
        asm volatile("barrier.cluster.wait.aligned;"   ::: "memory");
    }
}

// ============================================================================
// Epilogue: gather at positions, classifier, sigmoid.
// out layout: logits(64x2) | probs(64x2) | target(64x512)
// ============================================================================
__global__ void __launch_bounds__(512)
epilogue(const int* __restrict__ pos, const float* __restrict__ wcls,
         const float* __restrict__ bcls, float* __restrict__ out)
{
    __shared__ float s0[512], s1[512];
    int b = blockIdx.x, i = threadIdx.x;
    int t = pos[b];
    float y = d_Y1[((size_t)t*64 + b) * 512 + i];
    out[256 + b*512 + i] = y;
    s0[i] = y * wcls[i];
    s1[i] = y * wcls[512 + i];
    __syncthreads();
    for (int st = 256; st > 0; st >>= 1) {
        if (i < st) { s0[i] += s0[i+st]; s1[i] += s1[i+st]; }
        __syncthreads();
    }
    if (i == 0) {
        float l0 = s0[0] + bcls[0], l1 = s1[0] + bcls[1];
        out[b*2+0] = l0;            out[b*2+1] = l1;
        out[128 + b*2+0] = 1.f/(1.f+expf(-l0));
        out[128 + b*2+1] = 1.f/(1.f+expf(-l1));
    }
}

// ============================================================================
extern "C" void kernel_launch(void* const* d_in, const int* in_sizes, int n_in,
                              void* d_out, int out_size)
{
    const float *emb=0,*wih0=0,*whh0=0,*bih0=0,*bhh0=0;
    const float *wih1=0,*whh1=0,*bih1=0,*bhh1=0,*wcls=0,*bcls=0;
    const int *ctx=0,*pos=0;
    int nwhh = 0, nb = 0;
    for (int i = 0; i < n_in; i++) {
        int s = in_sizes[i]; const void* p = d_in[i];
        switch (s) {
            case 30000000: emb  = (const float*)p; break;
            case 614400:   wih0 = (const float*)p; break;
            case 1048576:  wih1 = (const float*)p; break;
            case 524288:   if (nwhh++ == 0) whh0 = (const float*)p;
                           else             whh1 = (const float*)p; break;
            case 2048:     if (nb == 0) bih0 = (const float*)p;
                           else if (nb == 1) bhh0 = (const float*)p;
                           else if (nb == 2) bih1 = (const float*)p;
                           else              bhh1 = (const float*)p;
                           nb++; break;
            case 1024:     wcls = (const float*)p; break;
            case 2:        bcls = (const float*)p; break;
            case 32768:    ctx  = (const int*)p; break;
            case 64:       pos  = (const int*)p; break;
            default: break;
        }
    }

    dim3 ggrid(16, 256);
    gemm_inp<<<ggrid, 256>>>(emb, ctx, wih0, bih0, bhh0, EMB, 0);
    lstm_rec<<<128, 256>>>(whh0, 0);
    gemm_inp<<<ggrid, 256>>>(emb, ctx, wih1, bih1, bhh1, 512, 1);
    lstm_rec<<<128, 256>>>(whh1, 1);
    epilogue<<<64, 512>>>(pos, wcls, bcls, (float*)d_out);
}

// round 9
// speedup vs baseline: 1.1608x; 1.1133x over previous
#include <cuda_runtime.h>
#include <cuda_bf16.h>
#include <math.h>
#include <stdint.h>

#define VOCAB 100000
#define EMB   300
#define HID   256
#define BATCH 64
#define SEQ   512
#define NROWS (SEQ*BATCH)   /* 32768 */
#define GCOLS 2048          /* 2 dirs * 4 gates * 256 */
#define K3MAX 1536          /* max concatenated K (layer 1: 3*512) */

// ---------------- static scratch (no allocations allowed) -------------------
__device__ float d_G [(size_t)NROWS * GCOLS];     // gate preactivations
__device__ float d_Y0[(size_t)NROWS * 512];       // layer-0 output (t,b,2H)
__device__ float d_Y1[(size_t)NROWS * 512];       // layer-1 output (t,b,2H)
__device__ __nv_bfloat16 d_A2[(size_t)NROWS * K3MAX];  // [Ahi|Alo|Ahi]
__device__ __nv_bfloat16 d_W2[(size_t)GCOLS * K3MAX];  // [Whi|Whi|Wlo]

// ---------------- packed fp32x2 helpers (lstm_rec, unchanged) ---------------
__device__ __forceinline__ void fma2(unsigned long long& acc,
                                     unsigned long long a, unsigned long long b) {
    asm("fma.rn.f32x2 %0, %1, %2, %0;" : "+l"(acc) : "l"(a), "l"(b));
}
__device__ __forceinline__ float2 unpk(unsigned long long v) {
    float2 f;
    asm("mov.b64 {%0, %1}, %2;" : "=f"(f.x), "=f"(f.y) : "l"(v));
    return f;
}

// ============================================================================
// Conversion prepasses: fp32 -> split bf16, concatenated along K.
//   A row: [hi | lo | hi]   W row: [hi | hi | lo]
// ============================================================================
__global__ void conv_a(const float* __restrict__ emb, const int* __restrict__ tokens,
                       int layer)
{
    int r = blockIdx.x;                    // r = t*64 + b
    const float* src; int K, Kp, stride;
    if (layer == 0) {
        int b = r & 63, t = r >> 6;
        src = emb + (size_t)tokens[b * SEQ + t] * EMB;
        K = 300; Kp = 320; stride = 960;
    } else {
        src = d_Y0 + (size_t)r * 512;
        K = 512; Kp = 512; stride = 1536;
    }
    __nv_bfloat16* row = d_A2 + (size_t)r * stride;
    for (int c = threadIdx.x; c < Kp; c += blockDim.x) {
        float x = (c < K) ? src[c] : 0.f;
        __nv_bfloat16 h = __float2bfloat16(x);
        row[c]        = h;
        row[Kp + c]   = __float2bfloat16(x - __bfloat162float(h));
        row[2*Kp + c] = h;
    }
}

__global__ void conv_w(const float* __restrict__ w, int layer)
{
    int r = blockIdx.x;                    // gate-column index (2048)
    int K, Kp, stride;
    if (layer == 0) { K = 300; Kp = 320; stride = 960; }
    else            { K = 512; Kp = 512; stride = 1536; }
    const float* src = w + (size_t)r * K;
    __nv_bfloat16* row = d_W2 + (size_t)r * stride;
    for (int c = threadIdx.x; c < Kp; c += blockDim.x) {
        float x = (c < K) ? src[c] : 0.f;
        __nv_bfloat16 h = __float2bfloat16(x);
        row[c]        = h;
        row[Kp + c]   = h;
        row[2*Kp + c] = __float2bfloat16(x - __bfloat162float(h));
    }
}

// ============================================================================
// HMMA GEMM: d_G[128x128 tile] = A2 . W2^T + bias1 + bias2
// 128x128 CTA tile, BK=32, 256 thr = 8 warps, warp tile 64x32 (4x4 m16n8k16).
// SMEM rows padded to 40 bf16 (80B = 5*16B): 16B-aligned, LDSM conflict-free.
// ============================================================================
#define SROW 40
#define BUFE (128*SROW)     /* elems per buffer */

__device__ __forceinline__ void ldsm_x4(uint32_t& r0, uint32_t& r1,
                                        uint32_t& r2, uint32_t& r3, uint32_t a) {
    asm volatile("ldmatrix.sync.aligned.m8n8.x4.shared.b16 {%0,%1,%2,%3}, [%4];"
                 : "=r"(r0), "=r"(r1), "=r"(r2), "=r"(r3) : "r"(a));
}
__device__ __forceinline__ void ldsm_x2(uint32_t& r0, uint32_t& r1, uint32_t a) {
    asm volatile("ldmatrix.sync.aligned.m8n8.x2.shared.b16 {%0,%1}, [%2];"
                 : "=r"(r0), "=r"(r1) : "r"(a));
}
__device__ __forceinline__ void mma16816(float* d, const uint32_t* a, const uint32_t* b) {
    asm volatile("mma.sync.aligned.m16n8k16.row.col.f32.bf16.bf16.f32 "
                 "{%0,%1,%2,%3}, {%4,%5,%6,%7}, {%8,%9}, {%0,%1,%2,%3};"
                 : "+f"(d[0]), "+f"(d[1]), "+f"(d[2]), "+f"(d[3])
                 : "r"(a[0]), "r"(a[1]), "r"(a[2]), "r"(a[3]), "r"(b[0]), "r"(b[1]));
}

__global__ void __launch_bounds__(256)
hmma_gemm(const float* __restrict__ b1, const float* __restrict__ b2, int Kp3)
{
    __shared__ __align__(16) __nv_bfloat16 As[2][128][SROW];
    __shared__ __align__(16) __nv_bfloat16 Bs[2][128][SROW];
    __shared__ float bsum[128];

    const int tid = threadIdx.x, lane = tid & 31, w = tid >> 5;
    const int bn = blockIdx.x, bm = blockIdx.y;
    const int wm = (w & 1) * 64, wn = (w >> 1) * 32;

    if (tid < 128) { int c = bn * 128 + tid; bsum[tid] = b1[c] + b2[c]; }

    const __nv_bfloat16* gA = d_A2 + (size_t)(bm * 128) * Kp3;
    const __nv_bfloat16* gB = d_W2 + (size_t)(bn * 128) * Kp3;

    // loader: 512 uint4 per matrix per iter / 256 thr = 2 each
    const int i0 = tid, i1 = tid + 256;
    const int ar0 = i0 >> 2, ac0 = (i0 & 3) * 8;
    const int ar1 = i1 >> 2, ac1 = (i1 & 3) * 8;

    float acc[4][4][4];
#pragma unroll
    for (int m = 0; m < 4; m++)
#pragma unroll
        for (int n = 0; n < 4; n++)
#pragma unroll
            for (int q = 0; q < 4; q++) acc[m][n][q] = 0.f;

    uint32_t sA = (uint32_t)__cvta_generic_to_shared(&As[0][0][0]);
    uint32_t sB = (uint32_t)__cvta_generic_to_shared(&Bs[0][0][0]);

    const int nk = Kp3 / 32;
    // prologue: tile 0
    {
        *(uint4*)&As[0][ar0][ac0] = *(const uint4*)(gA + (size_t)ar0 * Kp3 + ac0);
        *(uint4*)&As[0][ar1][ac1] = *(const uint4*)(gA + (size_t)ar1 * Kp3 + ac1);
        *(uint4*)&Bs[0][ar0][ac0] = *(const uint4*)(gB + (size_t)ar0 * Kp3 + ac0);
        *(uint4*)&Bs[0][ar1][ac1] = *(const uint4*)(gB + (size_t)ar1 * Kp3 + ac1);
    }
    __syncthreads();

    for (int kt = 0; kt < nk; kt++) {
        const int buf = kt & 1;
        if (kt + 1 < nk) {
            const int kb = (kt + 1) * 32, nb = buf ^ 1;
            *(uint4*)&As[nb][ar0][ac0] = *(const uint4*)(gA + (size_t)ar0 * Kp3 + kb + ac0);
            *(uint4*)&As[nb][ar1][ac1] = *(const uint4*)(gA + (size_t)ar1 * Kp3 + kb + ac1);
            *(uint4*)&Bs[nb][ar0][ac0] = *(const uint4*)(gB + (size_t)ar0 * Kp3 + kb + ac0);
            *(uint4*)&Bs[nb][ar1][ac1] = *(const uint4*)(gB + (size_t)ar1 * Kp3 + kb + ac1);
        }
        const uint32_t bA = sA + buf * (BUFE * 2);
        const uint32_t bB = sB + buf * (BUFE * 2);
#pragma unroll
        for (int ks = 0; ks < 2; ks++) {
            const int k0 = ks * 16;
            uint32_t a[4][4], bf[4][2];
#pragma unroll
            for (int mt = 0; mt < 4; mt++) {
                uint32_t ad = bA + (((wm + mt*16 + (lane & 15)) * SROW
                                     + k0 + (lane >> 4) * 8) << 1);
                ldsm_x4(a[mt][0], a[mt][1], a[mt][2], a[mt][3], ad);
            }
#pragma unroll
            for (int nt = 0; nt < 4; nt++) {
                uint32_t ad = bB + (((wn + nt*8 + (lane & 7)) * SROW
                                     + k0 + ((lane >> 3) & 1) * 8) << 1);
                ldsm_x2(bf[nt][0], bf[nt][1], ad);
            }
#pragma unroll
            for (int mt = 0; mt < 4; mt++)
#pragma unroll
                for (int nt = 0; nt < 4; nt++)
                    mma16816(acc[mt][nt], a[mt], bf[nt]);
        }
        __syncthreads();
    }

    // epilogue: d frag: (row=l/4, col=2*(l%4)) & (+1); d2/d3: row+8
#pragma unroll
    for (int mt = 0; mt < 4; mt++) {
        int r0 = bm * 128 + wm + mt * 16 + (lane >> 2);
#pragma unroll
        for (int nt = 0; nt < 4; nt++) {
            int c  = wn + nt * 8 + (lane & 3) * 2;
            int cg = bn * 128 + c;
            float2 v0 = make_float2(acc[mt][nt][0] + bsum[c],
                                    acc[mt][nt][1] + bsum[c + 1]);
            float2 v1 = make_float2(acc[mt][nt][2] + bsum[c],
                                    acc[mt][nt][3] + bsum[c + 1]);
            *(float2*)&d_G[(size_t)r0 * GCOLS + cg]       = v0;
            *(float2*)&d_G[(size_t)(r0 + 8) * GCOLS + cg] = v1;
        }
    }
}

// ============================================================================
// Persistent LSTM recurrence (frozen from the 9034us passing kernel).
// ============================================================================
__global__ void __cluster_dims__(8,1,1) __launch_bounds__(256,1)
lstm_rec(const float* __restrict__ whh, int layer)
{
    __shared__ __align__(16) float h_sm[2][8][256];
    __shared__ float ps[2][4][8][32];

    float* Y = layer ? d_Y1 : d_Y0;
    const int tid = threadIdx.x;
    const int j  = tid & 31;
    const int g  = (tid >> 5) & 3;
    const int kh = tid >> 7;
    const int hc = blockIdx.x & 7;
    const int cid = blockIdx.x >> 3;
    const int d  = cid & 1;
    const int B0 = (cid >> 1) * 8;

    ulonglong2 w2[32];
    {
        const ulonglong2* wp = (const ulonglong2*)
            (whh + ((size_t)d*1024 + g*256 + hc*32 + j) * 256 + kh*128);
#pragma unroll
        for (int kk = 0; kk < 32; kk++) w2[kk] = wp[kk];
    }
    {
        float* hz = &h_sm[0][0][0];
        for (int i = tid; i < 2*8*256; i += 256) hz[i] = 0.f;
    }
    const int ub = tid >> 5, uj = tid & 31;
    float creg = 0.f;
    __syncthreads();
    asm volatile("barrier.cluster.arrive.aligned;" ::: "memory");
    asm volatile("barrier.cluster.wait.aligned;"   ::: "memory");

    uint32_t base_l0 = (uint32_t)__cvta_generic_to_shared(&h_sm[0][ub][hc*32+uj]);
    uint32_t base_l1 = (uint32_t)__cvta_generic_to_shared(&h_sm[1][ub][hc*32+uj]);
    const int kq0 = kh * 32;

    for (int t = 0; t < SEQ; t++) {
        const int p = t & 1;
        size_t gb = ((size_t)t*64 + B0 + ub) * GCOLS + (size_t)d*1024 + hc*32 + uj;
        float gp0 = d_G[gb];
        float gp1 = d_G[gb + 256];
        float gp2 = d_G[gb + 512];
        float gp3 = d_G[gb + 768];

        const ulonglong2* hb = (const ulonglong2*)&h_sm[p][0][0];
        unsigned long long acc2[8];
#pragma unroll
        for (int b = 0; b < 8; b++) acc2[b] = 0ull;
#pragma unroll
        for (int kk = 0; kk < 32; kk++) {
            ulonglong2 wv = w2[kk];
#pragma unroll
            for (int b = 0; b < 8; b++) {
                ulonglong2 hv = hb[b*64 + kq0 + kk];
                fma2(acc2[b], wv.x, hv.x);
                fma2(acc2[b], wv.y, hv.y);
            }
        }
#pragma unroll
        for (int b = 0; b < 8; b++) {
            float2 u = unpk(acc2[b]);
            ps[kh][g][b][j] = u.x + u.y;
        }
        __syncthreads();

        float si = ps[0][0][ub][uj] + ps[1][0][ub][uj] + gp0;
        float sf = ps[0][1][ub][uj] + ps[1][1][ub][uj] + gp1;
        float sg = ps[0][2][ub][uj] + ps[1][2][ub][uj] + gp2;
        float so = ps[0][3][ub][uj] + ps[1][3][ub][uj] + gp3;
        float iv = 1.f / (1.f + expf(-si));
        float fv = 1.f / (1.f + expf(-sf));
        float ov = 1.f / (1.f + expf(-so));
        creg = fv * creg + iv * tanhf(sg);
        float hnew = ov * tanhf(creg);

        Y[((size_t)t*64 + B0 + ub) * 512 + (size_t)d*256 + hc*32 + uj] = hnew;

        uint32_t la = p ? base_l0 : base_l1;
#pragma unroll
        for (unsigned r = 0; r < 8; r++) {
            uint32_t ra;
            asm volatile("mapa.shared::cluster.u32 %0, %1, %2;"
                         : "=r"(ra) : "r"(la), "r"(r));
            asm volatile("st.shared::cluster.f32 [%0], %1;"
                         :: "r"(ra), "f"(hnew) : "memory");
        }
        asm volatile("barrier.cluster.arrive.aligned;" ::: "memory");
        asm volatile("barrier.cluster.wait.aligned;"   ::: "memory");
    }
}

// ============================================================================
// Epilogue (frozen): gather at positions, classifier, sigmoid.
// out layout: logits(64x2) | probs(64x2) | target(64x512)
// ============================================================================
__global__ void __launch_bounds__(512)
epilogue(const int* __restrict__ pos, const float* __restrict__ wcls,
         const float* __restrict__ bcls, float* __restrict__ out)
{
    __shared__ float s0[512], s1[512];
    int b = blockIdx.x, i = threadIdx.x;
    int t = pos[b];
    float y = d_Y1[((size_t)t*64 + b) * 512 + i];
    out[256 + b*512 + i] = y;
    s0[i] = y * wcls[i];
    s1[i] = y * wcls[512 + i];
    __syncthreads();
    for (int st = 256; st > 0; st >>= 1) {
        if (i < st) { s0[i] += s0[i+st]; s1[i] += s1[i+st]; }
        __syncthreads();
    }
    if (i == 0) {
        float l0 = s0[0] + bcls[0], l1 = s1[0] + bcls[1];
        out[b*2+0] = l0;            out[b*2+1] = l1;
        out[128 + b*2+0] = 1.f/(1.f+expf(-l0));
        out[128 + b*2+1] = 1.f/(1.f+expf(-l1));
    }
}

// ============================================================================
extern "C" void kernel_launch(void* const* d_in, const int* in_sizes, int n_in,
                              void* d_out, int out_size)
{
    const float *emb=0,*wih0=0,*whh0=0,*bih0=0,*bhh0=0;
    const float *wih1=0,*whh1=0,*bih1=0,*bhh1=0,*wcls=0,*bcls=0;
    const int *ctx=0,*pos=0;
    int nwhh = 0, nb = 0;
    for (int i = 0; i < n_in; i++) {
        int s = in_sizes[i]; const void* p = d_in[i];
        switch (s) {
            case 30000000: emb  = (const float*)p; break;
            case 614400:   wih0 = (const float*)p; break;
            case 1048576:  wih1 = (const float*)p; break;
            case 524288:   if (nwhh++ == 0) whh0 = (const float*)p;
                           else             whh1 = (const float*)p; break;
            case 2048:     if (nb == 0) bih0 = (const float*)p;
                           else if (nb == 1) bhh0 = (const float*)p;
                           else if (nb == 2) bih1 = (const float*)p;
                           else              bhh1 = (const float*)p;
                           nb++; break;
            case 1024:     wcls = (const float*)p; break;
            case 2:        bcls = (const float*)p; break;
            case 32768:    ctx  = (const int*)p; break;
            case 64:       pos  = (const int*)p; break;
            default: break;
        }
    }

    dim3 ggrid(16, 256);
    // layer 0
    conv_a<<<NROWS, 128>>>(emb, ctx, 0);
    conv_w<<<GCOLS, 128>>>(wih0, 0);
    hmma_gemm<<<ggrid, 256>>>(bih0, bhh0, 960);
    lstm_rec<<<128, 256>>>(whh0, 0);
    // layer 1
    conv_a<<<NROWS, 128>>>(emb, ctx, 1);
    conv_w<<<GCOLS, 128>>>(wih1, 1);
    hmma_gemm<<<ggrid, 256>>>(bih1, bhh1, 1536);
    lstm_rec<<<128, 256>>>(whh1, 1);
    // classifier
    epilogue<<<64, 512>>>(pos, wcls, bcls, (float*)d_out);
}